// round 6
// baseline (speedup 1.0000x reference)
#include <cuda_runtime.h>
#include <math.h>

// Problem constants
#define BATCH 8
#define NH    8
#define SEQQ  1024
#define SEQK  1024
#define DIM   512
#define HD    64
#define MROWS (BATCH*SEQQ)   // 8192

#define LN_EPS   1e-5f
#define MASK_INF 1e38f

#define EPI_BIAS       0
#define EPI_RELU_RESID 3

static __device__ float g_q [BATCH*SEQQ*DIM];
static __device__ float g_k [BATCH*SEQK*DIM];
static __device__ float g_v [BATCH*SEQK*DIM];
static __device__ float g_t0[BATCH*SEQQ*DIM];
static __device__ float g_t1[BATCH*SEQQ*DIM];

// ---------------------------------------------------------------------------
// helpers
// ---------------------------------------------------------------------------
__device__ __forceinline__ unsigned f2tf(float x) {
    unsigned u;
    asm("cvt.rna.tf32.f32 %0, %1;" : "=r"(u) : "f"(x));
    return u;
}

__device__ __forceinline__ void mma_tf32(float* c, const unsigned* a, const unsigned* b) {
    asm volatile(
        "mma.sync.aligned.m16n8k8.row.col.f32.tf32.tf32.f32 "
        "{%0,%1,%2,%3},{%4,%5,%6,%7},{%8,%9},{%0,%1,%2,%3};"
        : "+f"(c[0]), "+f"(c[1]), "+f"(c[2]), "+f"(c[3])
        : "r"(a[0]), "r"(a[1]), "r"(a[2]), "r"(a[3]), "r"(b[0]), "r"(b[1]));
}

__device__ __forceinline__ void ldsm_x4(unsigned& r0, unsigned& r1,
                                        unsigned& r2, unsigned& r3, unsigned a) {
    asm volatile("ldmatrix.sync.aligned.m8n8.x4.shared.b16 {%0,%1,%2,%3}, [%4];"
        : "=r"(r0), "=r"(r1), "=r"(r2), "=r"(r3) : "r"(a));
}

__device__ __forceinline__ unsigned sm_addr(const void* p) {
    return (unsigned)__cvta_generic_to_shared(p);
}

// ---------------------------------------------------------------------------
// Dense NN GEMM: C[M,N] = A[M,K] @ B[K,N] + epilogue. BM=BN=128, BK=16.
// Double-buffered smem; A m-major stride 20, B stored n-major stride 20.
// All fragment loads via ldmatrix.x4.
// ---------------------------------------------------------------------------
template<int EPI>
__global__ __launch_bounds__(256, 2)
void gemm_nn_tc(const float* __restrict__ A, const float* __restrict__ B,
                float* __restrict__ C, int M, int N, int K,
                const float* __restrict__ bias, const float* __restrict__ R)
{
    __shared__ __align__(16) unsigned As[2][128*20];   // [m][k] tf32
    __shared__ __align__(16) unsigned Bs[2][128*20];   // [n][k] tf32 (n-major)

    const int tid  = threadIdx.x;
    const int m0   = blockIdx.y * 128;
    const int n0   = blockIdx.x * 128;
    const int lane = tid & 31;
    const int warp = tid >> 5;
    const int mBase = (warp & 3) * 32;
    const int nBase = (warp >> 2) * 64;

    // staging coords (2 rounds of 256 threads)
    const int am [2] = { tid & 127,        (tid + 256) & 127 };
    const int akq[2] = { 4 * (tid >> 7),   4 * ((tid + 256) >> 7) };
    const int bkk[2] = { tid & 15,         (tid + 256) & 15 };
    const int bnc[2] = { 4 * (tid >> 4),   4 * ((tid + 256) >> 4) };

    // ldmatrix lane bases (byte addresses)
    unsigned aB[2], bB[2];
    {
        const int ar = mBase + (lane & 15);
        const int ac = 4 * (lane >> 4);
        const int br = nBase + 8 * (lane >> 4) + (lane & 7);
        const int bc = 4 * ((lane >> 3) & 1);
        aB[0] = sm_addr(&As[0][ar*20 + ac]);
        aB[1] = sm_addr(&As[1][ar*20 + ac]);
        bB[0] = sm_addr(&Bs[0][br*20 + bc]);
        bB[1] = sm_addr(&Bs[1][br*20 + bc]);
    }

    float acc[2][8][4];
    #pragma unroll
    for (int i = 0; i < 2; i++)
        #pragma unroll
        for (int j = 0; j < 8; j++)
            #pragma unroll
            for (int r = 0; r < 4; r++) acc[i][j][r] = 0.f;

    float4 ra[2], rb[2];

    // --- prologue: k-block 0 -> stage 0
    #pragma unroll
    for (int r = 0; r < 2; r++) {
        ra[r] = *(const float4*)(A + (size_t)(m0 + am[r]) * K + akq[r]);
        rb[r] = *(const float4*)(B + (size_t)bkk[r] * N + n0 + bnc[r]);
    }
    #pragma unroll
    for (int r = 0; r < 2; r++) {
        uint4 t = make_uint4(f2tf(ra[r].x), f2tf(ra[r].y), f2tf(ra[r].z), f2tf(ra[r].w));
        *(uint4*)&As[0][am[r]*20 + akq[r]] = t;
        Bs[0][(bnc[r]+0)*20 + bkk[r]] = f2tf(rb[r].x);
        Bs[0][(bnc[r]+1)*20 + bkk[r]] = f2tf(rb[r].y);
        Bs[0][(bnc[r]+2)*20 + bkk[r]] = f2tf(rb[r].z);
        Bs[0][(bnc[r]+3)*20 + bkk[r]] = f2tf(rb[r].w);
    }
    __syncthreads();

    int st = 0;
    for (int k0 = 16; k0 < K; k0 += 16) {
        // issue next k-block loads
        #pragma unroll
        for (int r = 0; r < 2; r++) {
            ra[r] = *(const float4*)(A + (size_t)(m0 + am[r]) * K + k0 + akq[r]);
            rb[r] = *(const float4*)(B + (size_t)(k0 + bkk[r]) * N + n0 + bnc[r]);
        }

        // compute current stage
        #pragma unroll
        for (int ks = 0; ks < 16; ks += 8) {
            unsigned a0[4], a1[4], b[8][2];
            ldsm_x4(a0[0], a0[1], a0[2], a0[3], aB[st] + ks*4);
            ldsm_x4(a1[0], a1[1], a1[2], a1[3], aB[st] + (16*20 + ks)*4);
            #pragma unroll
            for (int jp = 0; jp < 4; jp++)
                ldsm_x4(b[2*jp][0], b[2*jp][1], b[2*jp+1][0], b[2*jp+1][1],
                        bB[st] + (jp*16*20 + ks)*4);
            #pragma unroll
            for (int j = 0; j < 8; j++) {
                mma_tf32(acc[0][j], a0, b[j]);
                mma_tf32(acc[1][j], a1, b[j]);
            }
        }

        // store staged into other stage
        const int ns = st ^ 1;
        #pragma unroll
        for (int r = 0; r < 2; r++) {
            uint4 t = make_uint4(f2tf(ra[r].x), f2tf(ra[r].y), f2tf(ra[r].z), f2tf(ra[r].w));
            *(uint4*)&As[ns][am[r]*20 + akq[r]] = t;
            Bs[ns][(bnc[r]+0)*20 + bkk[r]] = f2tf(rb[r].x);
            Bs[ns][(bnc[r]+1)*20 + bkk[r]] = f2tf(rb[r].y);
            Bs[ns][(bnc[r]+2)*20 + bkk[r]] = f2tf(rb[r].z);
            Bs[ns][(bnc[r]+3)*20 + bkk[r]] = f2tf(rb[r].w);
        }
        __syncthreads();
        st = ns;
    }

    // final k-block
    #pragma unroll
    for (int ks = 0; ks < 16; ks += 8) {
        unsigned a0[4], a1[4], b[8][2];
        ldsm_x4(a0[0], a0[1], a0[2], a0[3], aB[st] + ks*4);
        ldsm_x4(a1[0], a1[1], a1[2], a1[3], aB[st] + (16*20 + ks)*4);
        #pragma unroll
        for (int jp = 0; jp < 4; jp++)
            ldsm_x4(b[2*jp][0], b[2*jp][1], b[2*jp+1][0], b[2*jp+1][1],
                    bB[st] + (jp*16*20 + ks)*4);
        #pragma unroll
        for (int j = 0; j < 8; j++) {
            mma_tf32(acc[0][j], a0, b[j]);
            mma_tf32(acc[1][j], a1, b[j]);
        }
    }

    // epilogue
    const int g = lane >> 2;
    const int q = lane & 3;
    #pragma unroll
    for (int i = 0; i < 2; i++) {
        #pragma unroll
        for (int rr = 0; rr < 2; rr++) {
            int row = m0 + mBase + i * 16 + g + rr * 8;
            #pragma unroll
            for (int j = 0; j < 8; j++) {
                int col = n0 + nBase + j * 8 + 2 * q;
                float v0 = acc[i][j][rr*2 + 0];
                float v1 = acc[i][j][rr*2 + 1];
                if (EPI == EPI_BIAS) {
                    v0 += bias[col]; v1 += bias[col + 1];
                } else { // EPI_RELU_RESID
                    v0 = R[(size_t)row*N + col    ] + fmaxf(v0 + bias[col    ], 0.f);
                    v1 = R[(size_t)row*N + col + 1] + fmaxf(v1 + bias[col + 1], 0.f);
                }
                *(float2*)(C + (size_t)row * N + col) = make_float2(v0, v1);
            }
        }
    }
}

// ---------------------------------------------------------------------------
// Fused flash attention:  O = qh + softmax(mask(scale * Qh K^T)) @ Vh
// Grid: (SEQQ/128, BATCH*NH). Block: 256 threads = 8 warps.
// Qs[128][68] (q-major), Ks[64][68] (key-major = n-major for S),
// Vs[64][68] (dim-major = n-major for PV), Ps 8x[16][68] per-warp P staging.
// All fragments via ldmatrix.x4; PV transpose via per-warp smem (no shuffles).
// ---------------------------------------------------------------------------
#define FLASH_WORDS (128*68 + 64*68 + 64*68 + 8*16*68 + 64)
#define FLASH_SMEM  (FLASH_WORDS * 4)

__global__ __launch_bounds__(256, 2)
void flash_tc(const float* __restrict__ Qm, const float* __restrict__ Km,
              const float* __restrict__ Vm,
              const float* __restrict__ pq, const float* __restrict__ pk,
              float* __restrict__ Om, float scale)
{
    extern __shared__ __align__(16) unsigned smem[];
    unsigned* Qs = smem;                 // [128][68]
    unsigned* Ks = Qs + 128*68;          // [64][68]  rows=key, cols=dim
    unsigned* Vs = Ks + 64*68;           // [64][68]  rows=dim, cols=key
    unsigned* Ps = Vs + 64*68;           // 8 x [16][68]
    float*    pks = (float*)(Ps + 8*16*68);

    const int bh = blockIdx.y;
    const int bz = bh >> 3, hz = bh & 7;
    const int m0 = blockIdx.x * 128;
    const int tid  = threadIdx.x;
    const int lane = tid & 31;
    const int w    = tid >> 5;
    const int g    = lane >> 2;
    const int q    = lane & 3;

    const size_t base = (size_t)bz * SEQQ * DIM + hz * HD;
    const float* Qp = Qm + base;
    const float* Kp = Km + base;
    const float* Vp = Vm + base;
    float*       Op = Om + base;

    const int row0 = m0 + w * 16 + g;

    // --- stage Q tile (once)
    #pragma unroll
    for (int r = 0; r < 8; r++) {
        int f = tid + r * 256;
        int m = f & 127, cq = 4 * (f >> 7);
        float4 t = *(const float4*)(Qp + (size_t)(m0 + m) * DIM + cq);
        *(uint4*)&Qs[m*68 + cq] =
            make_uint4(f2tf(t.x), f2tf(t.y), f2tf(t.z), f2tf(t.w));
    }

    // ldmatrix lane bases (bytes)
    const unsigned qB = sm_addr(&Qs[(w*16 + (lane & 15))*68 + 4*(lane >> 4)]);
    const unsigned kB = sm_addr(&Ks[(8*(lane >> 4) + (lane & 7))*68 + 4*((lane >> 3) & 1)]);
    const unsigned vB = sm_addr(&Vs[(8*(lane >> 4) + (lane & 7))*68 + 4*((lane >> 3) & 1)]);
    const unsigned pB = sm_addr(&Ps[w*1088 + (lane & 15)*68 + 4*(lane >> 4)]);
    unsigned* Pw = Ps + w * 1088;

    const float pq0 = pq[bz * SEQQ + row0];
    const float pq1 = pq[bz * SEQQ + row0 + 8];

    float o[8][4];
    #pragma unroll
    for (int j = 0; j < 8; j++)
        #pragma unroll
        for (int r = 0; r < 4; r++) o[j][r] = 0.f;

    float rm0 = -INFINITY, rm1 = -INFINITY;
    float rl0 = 0.f, rl1 = 0.f;

    __syncthreads();

    for (int t = 0; t < 16; t++) {
        const int n0 = t * 64;

        // --- stage K (key-major) and V (dim-major) + pk slice
        #pragma unroll
        for (int r = 0; r < 4; r++) {
            int f = tid + r * 256;
            int n = f & 63, kc = 4 * ((f >> 6) & 15);
            float4 kv = *(const float4*)(Kp + (size_t)(n0 + n) * DIM + kc);
            *(uint4*)&Ks[n*68 + kc] =
                make_uint4(f2tf(kv.x), f2tf(kv.y), f2tf(kv.z), f2tf(kv.w));
            float4 vv = *(const float4*)(Vp + (size_t)(n0 + n) * DIM + kc);
            Vs[(kc+0)*68 + n] = f2tf(vv.x);
            Vs[(kc+1)*68 + n] = f2tf(vv.y);
            Vs[(kc+2)*68 + n] = f2tf(vv.z);
            Vs[(kc+3)*68 + n] = f2tf(vv.w);
        }
        if (tid < 64) pks[tid] = pk[bz * SEQK + n0 + tid];
        __syncthreads();

        // --- S = Q K^T
        float s[8][4];
        #pragma unroll
        for (int j = 0; j < 8; j++)
            #pragma unroll
            for (int r = 0; r < 4; r++) s[j][r] = 0.f;

        #pragma unroll
        for (int c = 0; c < 8; c++) {
            unsigned a[4], kb[8][2];
            ldsm_x4(a[0], a[1], a[2], a[3], qB + 32*c);
            #pragma unroll
            for (int jp = 0; jp < 4; jp++)
                ldsm_x4(kb[2*jp][0], kb[2*jp][1], kb[2*jp+1][0], kb[2*jp+1][1],
                        kB + (jp*1088 + 8*c)*4);
            #pragma unroll
            for (int j = 0; j < 8; j++)
                mma_tf32(s[j], a, kb[j]);
        }

        // --- mask + online softmax
        float mt0 = -INFINITY, mt1 = -INFINITY;
        #pragma unroll
        for (int j = 0; j < 8; j++) {
            const float pka = pks[8*j + 2*q];
            const float pkb = pks[8*j + 2*q + 1];
            float x0 = pq0 * (s[j][0] * scale) - (1.f - pq0) * MASK_INF;
            float x1 = pq0 * (s[j][1] * scale) - (1.f - pq0) * MASK_INF;
            float x2 = pq1 * (s[j][2] * scale) - (1.f - pq1) * MASK_INF;
            float x3 = pq1 * (s[j][3] * scale) - (1.f - pq1) * MASK_INF;
            x0 = pka * x0 - (1.f - pka) * MASK_INF;
            x1 = pkb * x1 - (1.f - pkb) * MASK_INF;
            x2 = pka * x2 - (1.f - pka) * MASK_INF;
            x3 = pkb * x3 - (1.f - pkb) * MASK_INF;
            s[j][0] = x0; s[j][1] = x1; s[j][2] = x2; s[j][3] = x3;
            mt0 = fmaxf(mt0, fmaxf(x0, x1));
            mt1 = fmaxf(mt1, fmaxf(x2, x3));
        }
        mt0 = fmaxf(mt0, __shfl_xor_sync(0xffffffffu, mt0, 1));
        mt0 = fmaxf(mt0, __shfl_xor_sync(0xffffffffu, mt0, 2));
        mt1 = fmaxf(mt1, __shfl_xor_sync(0xffffffffu, mt1, 1));
        mt1 = fmaxf(mt1, __shfl_xor_sync(0xffffffffu, mt1, 2));

        const float mn0 = fmaxf(rm0, mt0);
        const float mn1 = fmaxf(rm1, mt1);
        const float sf0 = __expf(rm0 - mn0);
        const float sf1 = __expf(rm1 - mn1);
        rm0 = mn0; rm1 = mn1;

        float ps0 = 0.f, ps1 = 0.f;
        #pragma unroll
        for (int j = 0; j < 8; j++) {
            s[j][0] = __expf(s[j][0] - mn0); ps0 += s[j][0];
            s[j][1] = __expf(s[j][1] - mn0); ps0 += s[j][1];
            s[j][2] = __expf(s[j][2] - mn1); ps1 += s[j][2];
            s[j][3] = __expf(s[j][3] - mn1); ps1 += s[j][3];
        }
        ps0 += __shfl_xor_sync(0xffffffffu, ps0, 1);
        ps0 += __shfl_xor_sync(0xffffffffu, ps0, 2);
        ps1 += __shfl_xor_sync(0xffffffffu, ps1, 1);
        ps1 += __shfl_xor_sync(0xffffffffu, ps1, 2);
        rl0 = rl0 * sf0 + ps0;
        rl1 = rl1 * sf1 + ps1;

        #pragma unroll
        for (int j = 0; j < 8; j++) {
            o[j][0] *= sf0; o[j][1] *= sf0;
            o[j][2] *= sf1; o[j][3] *= sf1;
        }

        // --- stage P (per-warp, tf32), C-frag -> A-frag layout in smem
        #pragma unroll
        for (int c = 0; c < 8; c++) {
            *(uint2*)(Pw + g*68 + 8*c + 2*q) =
                make_uint2(f2tf(s[c][0]), f2tf(s[c][1]));
            *(uint2*)(Pw + (g+8)*68 + 8*c + 2*q) =
                make_uint2(f2tf(s[c][2]), f2tf(s[c][3]));
        }
        __syncwarp();

        // --- O += P @ V
        #pragma unroll
        for (int c = 0; c < 8; c++) {
            unsigned ap[4], vb[8][2];
            ldsm_x4(ap[0], ap[1], ap[2], ap[3], pB + 32*c);
            #pragma unroll
            for (int jp = 0; jp < 4; jp++)
                ldsm_x4(vb[2*jp][0], vb[2*jp][1], vb[2*jp+1][0], vb[2*jp+1][1],
                        vB + (jp*1088 + 8*c)*4);
            #pragma unroll
            for (int j = 0; j < 8; j++)
                mma_tf32(o[j], ap, vb[j]);
        }
        __syncthreads();
    }

    // --- epilogue: O/l + qh residual
    const float il0 = 1.f / rl0;
    const float il1 = 1.f / rl1;
    #pragma unroll
    for (int j = 0; j < 8; j++) {
        const int col = 8*j + 2*q;
        float2 r0 = *(const float2*)(Qp + (size_t)row0 * DIM + col);
        float2 r1 = *(const float2*)(Qp + (size_t)(row0 + 8) * DIM + col);
        *(float2*)(Op + (size_t)row0 * DIM + col) =
            make_float2(o[j][0] * il0 + r0.x, o[j][1] * il0 + r0.y);
        *(float2*)(Op + (size_t)(row0 + 8) * DIM + col) =
            make_float2(o[j][2] * il1 + r1.x, o[j][3] * il1 + r1.y);
    }
}

// ---------------------------------------------------------------------------
// LayerNorm over last dim (512). One block (128 threads) per row.
// ---------------------------------------------------------------------------
__global__ __launch_bounds__(128)
void ln_k(const float* __restrict__ X, float* __restrict__ Y,
          const float* __restrict__ gamma, const float* __restrict__ beta)
{
    const long row = blockIdx.x;
    const float* x = X + row*DIM;
    const int tid = threadIdx.x;
    const int w = tid >> 5, l = tid & 31;
    __shared__ float sred[4];

    float v[4];
    #pragma unroll
    for (int i = 0; i < 4; i++) v[i] = x[tid + i*128];

    float s = v[0]+v[1]+v[2]+v[3];
    #pragma unroll
    for (int o = 16; o > 0; o >>= 1) s += __shfl_xor_sync(0xffffffffu, s, o);
    if (l == 0) sred[w] = s;
    __syncthreads();
    float mu = (sred[0]+sred[1]+sred[2]+sred[3]) * (1.f/DIM);
    __syncthreads();

    float sq = 0.f;
    #pragma unroll
    for (int i = 0; i < 4; i++) { v[i] -= mu; sq += v[i]*v[i]; }
    #pragma unroll
    for (int o = 16; o > 0; o >>= 1) sq += __shfl_xor_sync(0xffffffffu, sq, o);
    if (l == 0) sred[w] = sq;
    __syncthreads();
    const float var = (sred[0]+sred[1]+sred[2]+sred[3]) * (1.f/DIM);
    const float r = rsqrtf(var + LN_EPS);

    #pragma unroll
    for (int i = 0; i < 4; i++) {
        const int c = tid + i*128;
        Y[row*DIM + c] = v[i]*r*gamma[c] + beta[c];
    }
}

// ---------------------------------------------------------------------------
extern "C" void kernel_launch(void* const* d_in, const int* in_sizes, int n_in,
                              void* d_out, int out_size)
{
    (void)in_sizes; (void)n_in; (void)out_size;
    const float* queries = (const float*)d_in[0];
    const float* keys    = (const float*)d_in[1];
    const float* pq      = (const float*)d_in[2];
    const float* pk      = (const float*)d_in[3];
    // d_in[4] = num_heads (fixed 8)
    const float* Wq = (const float*)d_in[5];
    const float* bq = (const float*)d_in[6];
    const float* Wk = (const float*)d_in[7];
    const float* bk = (const float*)d_in[8];
    const float* Wv = (const float*)d_in[9];
    const float* bv = (const float*)d_in[10];
    const float* Wo = (const float*)d_in[11];
    const float* bo = (const float*)d_in[12];
    const float* g0 = (const float*)d_in[13];
    const float* b0 = (const float*)d_in[14];
    const float* g1 = (const float*)d_in[15];
    const float* b1 = (const float*)d_in[16];
    float* out = (float*)d_out;

    float *q, *k, *v, *t0, *t1;
    cudaGetSymbolAddress((void**)&q,  g_q);
    cudaGetSymbolAddress((void**)&k,  g_k);
    cudaGetSymbolAddress((void**)&v,  g_v);
    cudaGetSymbolAddress((void**)&t0, g_t0);
    cudaGetSymbolAddress((void**)&t1, g_t1);

    const float att_scale = 1.0f / sqrtf((float)DIM);

    // --- projections: q/k/v = X @ W + b   (8192x512 @ 512x512)
    {
        dim3 grid(DIM/128, MROWS/128, 1);
        gemm_nn_tc<EPI_BIAS><<<grid,256>>>(queries, Wq, q, MROWS, DIM, DIM, bq, 0);
        gemm_nn_tc<EPI_BIAS><<<grid,256>>>(keys,    Wk, k, MROWS, DIM, DIM, bk, 0);
        gemm_nn_tc<EPI_BIAS><<<grid,256>>>(keys,    Wv, v, MROWS, DIM, DIM, bv, 0);
    }

    // --- fused attention: t0 = qh + softmax(mask(QK^T)) V
    {
        cudaFuncSetAttribute(flash_tc, cudaFuncAttributeMaxDynamicSharedMemorySize,
                             FLASH_SMEM);
        dim3 grid(SEQQ/128, BATCH*NH);
        flash_tc<<<grid,256,FLASH_SMEM>>>(q, k, v, pq, pk, t0, att_scale);
    }

    // --- LN0 (in place)
    ln_k<<<MROWS, 128>>>(t0, t0, g0, b0);

    // --- t1 = t0 + relu(t0 @ Wo + bo)
    {
        dim3 grid(DIM/128, MROWS/128, 1);
        gemm_nn_tc<EPI_RELU_RESID><<<grid,256>>>(t0, Wo, t1, MROWS, DIM, DIM, bo, t0);
    }

    // --- LN1 -> out
    ln_k<<<MROWS, 128>>>(t1, out, g1, b1);
}

// round 7
// speedup vs baseline: 1.4875x; 1.4875x over previous
#include <cuda_runtime.h>
#include <math.h>

// Problem constants
#define BATCH 8
#define NH    8
#define SEQQ  1024
#define SEQK  1024
#define DIM   512
#define HD    64
#define MROWS (BATCH*SEQQ)   // 8192

#define LN_EPS   1e-5f
#define MASK_INF 1e38f

#define EPI_BIAS       0
#define EPI_RELU_RESID 3

static __device__ float g_q [BATCH*SEQQ*DIM];
static __device__ float g_k [BATCH*SEQK*DIM];
static __device__ float g_v [BATCH*SEQK*DIM];
static __device__ float g_t0[BATCH*SEQQ*DIM];
static __device__ float g_t1[BATCH*SEQQ*DIM];

// ---------------------------------------------------------------------------
// helpers
// ---------------------------------------------------------------------------
__device__ __forceinline__ unsigned f2tf(float x) {
    unsigned u;
    asm("cvt.rna.tf32.f32 %0, %1;" : "=r"(u) : "f"(x));
    return u;
}

__device__ __forceinline__ void mma_tf32(float* c, const unsigned* a, const unsigned* b) {
    asm volatile(
        "mma.sync.aligned.m16n8k8.row.col.f32.tf32.tf32.f32 "
        "{%0,%1,%2,%3},{%4,%5,%6,%7},{%8,%9},{%0,%1,%2,%3};"
        : "+f"(c[0]), "+f"(c[1]), "+f"(c[2]), "+f"(c[3])
        : "r"(a[0]), "r"(a[1]), "r"(a[2]), "r"(a[3]), "r"(b[0]), "r"(b[1]));
}

__device__ __forceinline__ void cp16(unsigned dst, const void* src) {
    asm volatile("cp.async.cg.shared.global [%0], [%1], 16;" :: "r"(dst), "l"(src));
}
__device__ __forceinline__ void cp_commit() {
    asm volatile("cp.async.commit_group;" ::: "memory");
}
template<int N>
__device__ __forceinline__ void cp_wait() {
    asm volatile("cp.async.wait_group %0;" :: "n"(N) : "memory");
}

__device__ __forceinline__ unsigned sm_addr(const void* p) {
    return (unsigned)__cvta_generic_to_shared(p);
}

// ---------------------------------------------------------------------------
// Dense NN GEMM: C[M,N] = A[M,K] @ B[K,N] + epilogue. BM=BN=128, BK=16.
// 4-stage cp.async pipeline; raw f32 in smem; cvt.rna at fragment load
// (numerically identical to converting before store).
// Dynamic smem: As 4*128*20 + Bs 4*16*136 floats = 75776 B.
// ---------------------------------------------------------------------------
#define GA_STRIDE 20
#define GB_STRIDE 136
#define GEMM_SMEM ((4*128*GA_STRIDE + 4*16*GB_STRIDE) * 4)

template<int EPI>
__global__ __launch_bounds__(256, 2)
void gemm_nn_tc(const float* __restrict__ A, const float* __restrict__ B,
                float* __restrict__ C, int M, int N, int K,
                const float* __restrict__ bias, const float* __restrict__ R)
{
    extern __shared__ __align__(16) float gsm[];
    float* As = gsm;                         // [4][128][20]
    float* Bs = gsm + 4*128*GA_STRIDE;       // [4][16][136]

    const int tid  = threadIdx.x;
    const int m0   = blockIdx.y * 128;
    const int n0   = blockIdx.x * 128;
    const int lane = tid & 31;
    const int warp = tid >> 5;
    const int g    = lane >> 2;
    const int q    = lane & 3;
    const int mBase = (warp & 3) * 32;
    const int nBase = (warp >> 2) * 64;

    // cp.async staging coords: 2 chunks (16B) each for A and B per thread
    const int amr[2] = { tid >> 2,          (tid + 256) >> 2 };          // A row
    const int amc[2] = { (tid & 3) * 4,     ((tid + 256) & 3) * 4 };     // A k-offset
    const int bkr[2] = { tid >> 5,          (tid + 256) >> 5 };          // B k-row
    const int bnc[2] = { (tid & 31) * 4,    ((tid + 256) & 31) * 4 };    // B n-offset

    float acc[2][8][4];
    #pragma unroll
    for (int i = 0; i < 2; i++)
        #pragma unroll
        for (int j = 0; j < 8; j++)
            #pragma unroll
            for (int r = 0; r < 4; r++) acc[i][j][r] = 0.f;

    const int NITER = K / 16;   // 32

    // --- prologue: issue stages 0..2
    #pragma unroll
    for (int s = 0; s < 3; s++) {
        const int k0 = s * 16;
        #pragma unroll
        for (int r = 0; r < 2; r++) {
            cp16(sm_addr(&As[(s*128 + amr[r])*GA_STRIDE + amc[r]]),
                 A + (size_t)(m0 + amr[r]) * K + k0 + amc[r]);
            cp16(sm_addr(&Bs[(s*16 + bkr[r])*GB_STRIDE + bnc[r]]),
                 B + (size_t)(k0 + bkr[r]) * N + n0 + bnc[r]);
        }
        cp_commit();
    }

    for (int it = 0; it < NITER; it++) {
        cp_wait<2>();
        __syncthreads();

        // issue stage it+3 (overwrites buffer consumed at it-1)
        if (it + 3 < NITER) {
            const int s  = (it + 3) & 3;
            const int k0 = (it + 3) * 16;
            #pragma unroll
            for (int r = 0; r < 2; r++) {
                cp16(sm_addr(&As[(s*128 + amr[r])*GA_STRIDE + amc[r]]),
                     A + (size_t)(m0 + amr[r]) * K + k0 + amc[r]);
                cp16(sm_addr(&Bs[(s*16 + bkr[r])*GB_STRIDE + bnc[r]]),
                     B + (size_t)(k0 + bkr[r]) * N + n0 + bnc[r]);
            }
        }
        cp_commit();   // always commit (possibly empty) to keep group count uniform

        // compute stage it
        const float* Asf = As + (size_t)(it & 3) * 128 * GA_STRIDE;
        const float* Bsf = Bs + (size_t)(it & 3) * 16 * GB_STRIDE;
        #pragma unroll
        for (int ks = 0; ks < 16; ks += 8) {
            unsigned a[2][4], b[8][2];
            #pragma unroll
            for (int i = 0; i < 2; i++) {
                int row = mBase + i * 16 + g;
                a[i][0] = f2tf(Asf[(row    )*GA_STRIDE + ks + q]);
                a[i][1] = f2tf(Asf[(row + 8)*GA_STRIDE + ks + q]);
                a[i][2] = f2tf(Asf[(row    )*GA_STRIDE + ks + q + 4]);
                a[i][3] = f2tf(Asf[(row + 8)*GA_STRIDE + ks + q + 4]);
            }
            #pragma unroll
            for (int j = 0; j < 8; j++) {
                int col = nBase + j * 8 + g;
                b[j][0] = f2tf(Bsf[(ks + q    )*GB_STRIDE + col]);
                b[j][1] = f2tf(Bsf[(ks + q + 4)*GB_STRIDE + col]);
            }
            #pragma unroll
            for (int i = 0; i < 2; i++)
                #pragma unroll
                for (int j = 0; j < 8; j++)
                    mma_tf32(acc[i][j], a[i], b[j]);
        }
        __syncthreads();
    }

    // --- epilogue
    #pragma unroll
    for (int i = 0; i < 2; i++) {
        #pragma unroll
        for (int rr = 0; rr < 2; rr++) {
            int row = m0 + mBase + i * 16 + g + rr * 8;
            #pragma unroll
            for (int j = 0; j < 8; j++) {
                int col = n0 + nBase + j * 8 + 2 * q;
                float v0 = acc[i][j][rr*2 + 0];
                float v1 = acc[i][j][rr*2 + 1];
                if (EPI == EPI_BIAS) {
                    v0 += bias[col]; v1 += bias[col + 1];
                } else { // EPI_RELU_RESID
                    v0 = R[(size_t)row*N + col    ] + fmaxf(v0 + bias[col    ], 0.f);
                    v1 = R[(size_t)row*N + col + 1] + fmaxf(v1 + bias[col + 1], 0.f);
                }
                *(float2*)(C + (size_t)row * N + col) = make_float2(v0, v1);
            }
        }
    }
}

// ---------------------------------------------------------------------------
// Fused flash attention (round-5 version, 340us state — known good).
// Grid: (SEQQ/128, BATCH*NH). Block: 256 threads = 8 warps.
// ---------------------------------------------------------------------------
#define KS_STRIDE 68
#define VS_STRIDE 72
#define FLASH_SMEM ((128*KS_STRIDE + 64*KS_STRIDE + 64*VS_STRIDE) * 4 + 64 * 4)

__global__ __launch_bounds__(256, 2)
void flash_tc(const float* __restrict__ Qm, const float* __restrict__ Km,
              const float* __restrict__ Vm,
              const float* __restrict__ pq, const float* __restrict__ pk,
              float* __restrict__ Om, float scale)
{
    extern __shared__ unsigned smem[];
    unsigned* Qs = smem;                       // [128][68]
    unsigned* Ks = Qs + 128 * KS_STRIDE;       // [64][68]
    unsigned* Vs = Ks + 64 * KS_STRIDE;        // [64][72]
    float*    pks = (float*)(Vs + 64 * VS_STRIDE);

    const int bh = blockIdx.y;
    const int bz = bh >> 3, hz = bh & 7;
    const int m0 = blockIdx.x * 128;
    const int tid  = threadIdx.x;
    const int lane = tid & 31;
    const int w    = tid >> 5;
    const int g    = lane >> 2;
    const int q    = lane & 3;

    const size_t base = (size_t)bz * SEQQ * DIM + hz * HD;
    const float* Qp = Qm + base;
    const float* Kp = Km + base;
    const float* Vp = Vm + base;
    float*       Op = Om + base;

    const int row0 = m0 + w * 16 + g;
    const int lrow = w * 16 + g;

    // --- stage Q tile into shared as tf32 (once)
    #pragma unroll
    for (int r = 0; r < 8; r++) {
        int f = tid + r * 256;
        int m = f >> 4, cq = (f & 15) << 2;
        float4 t = *(const float4*)(Qp + (size_t)(m0 + m) * DIM + cq);
        unsigned* dst = Qs + m * KS_STRIDE + cq;
        dst[0] = f2tf(t.x); dst[1] = f2tf(t.y);
        dst[2] = f2tf(t.z); dst[3] = f2tf(t.w);
    }

    const float pq0 = pq[bz * SEQQ + row0];
    const float pq1 = pq[bz * SEQQ + row0 + 8];

    float o[8][4];
    #pragma unroll
    for (int j = 0; j < 8; j++)
        #pragma unroll
        for (int r = 0; r < 4; r++) o[j][r] = 0.f;

    float rm0 = -INFINITY, rm1 = -INFINITY;
    float rl0 = 0.f, rl1 = 0.f;

    const int L0  = g * 4 + (q >> 1);
    const bool odd = (q & 1);

    __syncthreads();

    for (int t = 0; t < 16; t++) {
        const int n0 = t * 64;

        // --- load K/V tiles (64 keys x 64 dims) + pk slice
        #pragma unroll
        for (int r = 0; r < 4; r++) {
            int n  = (tid >> 4) + r * 16;
            int kc = (tid & 15) << 2;
            float4 kv = *(const float4*)(Kp + (size_t)(n0 + n) * DIM + kc);
            unsigned* kd = Ks + n * KS_STRIDE + kc;
            kd[0] = f2tf(kv.x); kd[1] = f2tf(kv.y);
            kd[2] = f2tf(kv.z); kd[3] = f2tf(kv.w);
            float4 vv = *(const float4*)(Vp + (size_t)(n0 + n) * DIM + kc);
            unsigned* vd = Vs + n * VS_STRIDE + kc;
            vd[0] = f2tf(vv.x); vd[1] = f2tf(vv.y);
            vd[2] = f2tf(vv.z); vd[3] = f2tf(vv.w);
        }
        if (tid < 64) pks[tid] = pk[bz * SEQK + n0 + tid];
        __syncthreads();

        // --- S = Q K^T  (16 x 64 per warp)
        float s[8][4];
        #pragma unroll
        for (int j = 0; j < 8; j++)
            #pragma unroll
            for (int r = 0; r < 4; r++) s[j][r] = 0.f;

        #pragma unroll
        for (int c = 0; c < 8; c++) {
            unsigned a[4];
            a[0] = Qs[(lrow    ) * KS_STRIDE + 8*c + q    ];
            a[1] = Qs[(lrow + 8) * KS_STRIDE + 8*c + q    ];
            a[2] = Qs[(lrow    ) * KS_STRIDE + 8*c + q + 4];
            a[3] = Qs[(lrow + 8) * KS_STRIDE + 8*c + q + 4];
            #pragma unroll
            for (int j = 0; j < 8; j++) {
                unsigned b[2];
                b[0] = Ks[(8*j + g) * KS_STRIDE + 8*c + q    ];
                b[1] = Ks[(8*j + g) * KS_STRIDE + 8*c + q + 4];
                mma_tf32(s[j], a, b);
            }
        }

        // --- mask + online softmax (registers)
        float mt0 = -INFINITY, mt1 = -INFINITY;
        #pragma unroll
        for (int j = 0; j < 8; j++) {
            const float pka = pks[8*j + 2*q];
            const float pkb = pks[8*j + 2*q + 1];
            float x0 = pq0 * (s[j][0] * scale) - (1.f - pq0) * MASK_INF;
            float x1 = pq0 * (s[j][1] * scale) - (1.f - pq0) * MASK_INF;
            float x2 = pq1 * (s[j][2] * scale) - (1.f - pq1) * MASK_INF;
            float x3 = pq1 * (s[j][3] * scale) - (1.f - pq1) * MASK_INF;
            x0 = pka * x0 - (1.f - pka) * MASK_INF;
            x1 = pkb * x1 - (1.f - pkb) * MASK_INF;
            x2 = pka * x2 - (1.f - pka) * MASK_INF;
            x3 = pkb * x3 - (1.f - pkb) * MASK_INF;
            s[j][0] = x0; s[j][1] = x1; s[j][2] = x2; s[j][3] = x3;
            mt0 = fmaxf(mt0, fmaxf(x0, x1));
            mt1 = fmaxf(mt1, fmaxf(x2, x3));
        }
        mt0 = fmaxf(mt0, __shfl_xor_sync(0xffffffffu, mt0, 1));
        mt0 = fmaxf(mt0, __shfl_xor_sync(0xffffffffu, mt0, 2));
        mt1 = fmaxf(mt1, __shfl_xor_sync(0xffffffffu, mt1, 1));
        mt1 = fmaxf(mt1, __shfl_xor_sync(0xffffffffu, mt1, 2));

        const float mn0 = fmaxf(rm0, mt0);
        const float mn1 = fmaxf(rm1, mt1);
        const float sf0 = __expf(rm0 - mn0);
        const float sf1 = __expf(rm1 - mn1);
        rm0 = mn0; rm1 = mn1;

        float ps0 = 0.f, ps1 = 0.f;
        #pragma unroll
        for (int j = 0; j < 8; j++) {
            s[j][0] = __expf(s[j][0] - mn0); ps0 += s[j][0];
            s[j][1] = __expf(s[j][1] - mn0); ps0 += s[j][1];
            s[j][2] = __expf(s[j][2] - mn1); ps1 += s[j][2];
            s[j][3] = __expf(s[j][3] - mn1); ps1 += s[j][3];
        }
        ps0 += __shfl_xor_sync(0xffffffffu, ps0, 1);
        ps0 += __shfl_xor_sync(0xffffffffu, ps0, 2);
        ps1 += __shfl_xor_sync(0xffffffffu, ps1, 1);
        ps1 += __shfl_xor_sync(0xffffffffu, ps1, 2);
        rl0 = rl0 * sf0 + ps0;
        rl1 = rl1 * sf1 + ps1;

        #pragma unroll
        for (int j = 0; j < 8; j++) {
            o[j][0] *= sf0; o[j][1] *= sf0;
            o[j][2] *= sf1; o[j][3] *= sf1;
        }

        // --- O += P @ V  (C-layout -> A-fragment via shuffles)
        #pragma unroll
        for (int c = 0; c < 8; c++) {
            float v0 = __shfl_sync(0xffffffffu, s[c][0], L0);
            float v1 = __shfl_sync(0xffffffffu, s[c][1], L0);
            float v2 = __shfl_sync(0xffffffffu, s[c][2], L0);
            float v3 = __shfl_sync(0xffffffffu, s[c][3], L0);
            float w0 = __shfl_sync(0xffffffffu, s[c][0], L0 + 2);
            float w1 = __shfl_sync(0xffffffffu, s[c][1], L0 + 2);
            float w2 = __shfl_sync(0xffffffffu, s[c][2], L0 + 2);
            float w3 = __shfl_sync(0xffffffffu, s[c][3], L0 + 2);
            unsigned pf[4];
            pf[0] = f2tf(odd ? v1 : v0);
            pf[1] = f2tf(odd ? v3 : v2);
            pf[2] = f2tf(odd ? w1 : w0);
            pf[3] = f2tf(odd ? w3 : w2);
            #pragma unroll
            for (int j = 0; j < 8; j++) {
                unsigned b[2];
                b[0] = Vs[(8*c + q    ) * VS_STRIDE + 8*j + g];
                b[1] = Vs[(8*c + q + 4) * VS_STRIDE + 8*j + g];
                mma_tf32(o[j], pf, b);
            }
        }
        __syncthreads();
    }

    // --- epilogue: O/l + qh residual
    const float il0 = 1.f / rl0;
    const float il1 = 1.f / rl1;
    #pragma unroll
    for (int j = 0; j < 8; j++) {
        const int col = 8*j + 2*q;
        float2 r0 = *(const float2*)(Qp + (size_t)row0 * DIM + col);
        float2 r1 = *(const float2*)(Qp + (size_t)(row0 + 8) * DIM + col);
        *(float2*)(Op + (size_t)row0 * DIM + col) =
            make_float2(o[j][0] * il0 + r0.x, o[j][1] * il0 + r0.y);
        *(float2*)(Op + (size_t)(row0 + 8) * DIM + col) =
            make_float2(o[j][2] * il1 + r1.x, o[j][3] * il1 + r1.y);
    }
}

// ---------------------------------------------------------------------------
// LayerNorm over last dim (512). One block (128 threads) per row.
// ---------------------------------------------------------------------------
__global__ __launch_bounds__(128)
void ln_k(const float* __restrict__ X, float* __restrict__ Y,
          const float* __restrict__ gamma, const float* __restrict__ beta)
{
    const long row = blockIdx.x;
    const float* x = X + row*DIM;
    const int tid = threadIdx.x;
    const int w = tid >> 5, l = tid & 31;
    __shared__ float sred[4];

    float v[4];
    #pragma unroll
    for (int i = 0; i < 4; i++) v[i] = x[tid + i*128];

    float s = v[0]+v[1]+v[2]+v[3];
    #pragma unroll
    for (int o = 16; o > 0; o >>= 1) s += __shfl_xor_sync(0xffffffffu, s, o);
    if (l == 0) sred[w] = s;
    __syncthreads();
    float mu = (sred[0]+sred[1]+sred[2]+sred[3]) * (1.f/DIM);
    __syncthreads();

    float sq = 0.f;
    #pragma unroll
    for (int i = 0; i < 4; i++) { v[i] -= mu; sq += v[i]*v[i]; }
    #pragma unroll
    for (int o = 16; o > 0; o >>= 1) sq += __shfl_xor_sync(0xffffffffu, sq, o);
    if (l == 0) sred[w] = sq;
    __syncthreads();
    const float var = (sred[0]+sred[1]+sred[2]+sred[3]) * (1.f/DIM);
    const float r = rsqrtf(var + LN_EPS);

    #pragma unroll
    for (int i = 0; i < 4; i++) {
        const int c = tid + i*128;
        Y[row*DIM + c] = v[i]*r*gamma[c] + beta[c];
    }
}

// ---------------------------------------------------------------------------
extern "C" void kernel_launch(void* const* d_in, const int* in_sizes, int n_in,
                              void* d_out, int out_size)
{
    (void)in_sizes; (void)n_in; (void)out_size;
    const float* queries = (const float*)d_in[0];
    const float* keys    = (const float*)d_in[1];
    const float* pq      = (const float*)d_in[2];
    const float* pk      = (const float*)d_in[3];
    // d_in[4] = num_heads (fixed 8)
    const float* Wq = (const float*)d_in[5];
    const float* bq = (const float*)d_in[6];
    const float* Wk = (const float*)d_in[7];
    const float* bk = (const float*)d_in[8];
    const float* Wv = (const float*)d_in[9];
    const float* bv = (const float*)d_in[10];
    const float* Wo = (const float*)d_in[11];
    const float* bo = (const float*)d_in[12];
    const float* g0 = (const float*)d_in[13];
    const float* b0 = (const float*)d_in[14];
    const float* g1 = (const float*)d_in[15];
    const float* b1 = (const float*)d_in[16];
    float* out = (float*)d_out;

    float *q, *k, *v, *t0, *t1;
    cudaGetSymbolAddress((void**)&q,  g_q);
    cudaGetSymbolAddress((void**)&k,  g_k);
    cudaGetSymbolAddress((void**)&v,  g_v);
    cudaGetSymbolAddress((void**)&t0, g_t0);
    cudaGetSymbolAddress((void**)&t1, g_t1);

    const float att_scale = 1.0f / sqrtf((float)DIM);

    cudaFuncSetAttribute(gemm_nn_tc<EPI_BIAS>,
                         cudaFuncAttributeMaxDynamicSharedMemorySize, GEMM_SMEM);
    cudaFuncSetAttribute(gemm_nn_tc<EPI_RELU_RESID>,
                         cudaFuncAttributeMaxDynamicSharedMemorySize, GEMM_SMEM);
    cudaFuncSetAttribute(flash_tc,
                         cudaFuncAttributeMaxDynamicSharedMemorySize, FLASH_SMEM);

    // --- projections: q/k/v = X @ W + b   (8192x512 @ 512x512)
    {
        dim3 grid(DIM/128, MROWS/128, 1);
        gemm_nn_tc<EPI_BIAS><<<grid,256,GEMM_SMEM>>>(queries, Wq, q, MROWS, DIM, DIM, bq, 0);
        gemm_nn_tc<EPI_BIAS><<<grid,256,GEMM_SMEM>>>(keys,    Wk, k, MROWS, DIM, DIM, bk, 0);
        gemm_nn_tc<EPI_BIAS><<<grid,256,GEMM_SMEM>>>(keys,    Wv, v, MROWS, DIM, DIM, bv, 0);
    }

    // --- fused attention: t0 = qh + softmax(mask(QK^T)) V
    {
        dim3 grid(SEQQ/128, BATCH*NH);
        flash_tc<<<grid,256,FLASH_SMEM>>>(q, k, v, pq, pk, t0, att_scale);
    }

    // --- LN0 (in place)
    ln_k<<<MROWS, 128>>>(t0, t0, g0, b0);

    // --- t1 = t0 + relu(t0 @ Wo + bo)
    {
        dim3 grid(DIM/128, MROWS/128, 1);
        gemm_nn_tc<EPI_RELU_RESID><<<grid,256,GEMM_SMEM>>>(t0, Wo, t1, MROWS, DIM, DIM, bo, t0);
    }

    // --- LN1 -> out
    ln_k<<<MROWS, 128>>>(t1, out, g1, b1);
}